// round 3
// baseline (speedup 1.0000x reference)
#include <cuda_runtime.h>
#include <math.h>

// Problem constants
#define Bb   2
#define Tt   2048
#define Dd   2048
#define Hh   16
#define HDd  128
#define DCc  512
#define DRr  64
#define MR   (Bb*Tt)          // 4096 rows

// ---------------- scratch (static device globals; no allocation) -------------
__device__ float g_ckv[MR*DCc];          // 2M
__device__ float g_cq [MR*DCc];          // 2M
__device__ float g_K  [MR*Dd];           // 8M
__device__ float g_V  [MR*Dd];           // 8M
__device__ float g_Q  [MR*Dd];           // 8M
__device__ float g_kr [MR*DRr];          // 256K
__device__ float g_qr [MR*Hh*DRr];       // 4M
__device__ float g_ctx[MR*Dd];           // 8M

// ---------------- generic tiled SGEMM: C[M,N] = A[M,K] @ B[K,N] (+bias) ------
// 128x128 tile, K-step 8, double-buffered shared memory.
#define GBM 128
#define GBN 128
#define GBK 8

__global__ __launch_bounds__(256)
void sgemm_kernel(const float* __restrict__ A, const float* __restrict__ B,
                  float* __restrict__ C, int M, int N, int K,
                  const float* __restrict__ bias)
{
    __shared__ float As[2][GBK][GBM];
    __shared__ float Bs[2][GBK][GBN];

    int tid = threadIdx.x;
    int tr  = tid / 16;          // 0..15
    int tc  = tid % 16;          // 0..15
    int row0 = blockIdx.y * GBM;
    int col0 = blockIdx.x * GBN;

    int a_row = tid >> 1;            // 0..127
    int a_col = (tid & 1) * 4;       // 0 or 4
    int b_row = tid >> 5;            // 0..7
    int b_col = (tid & 31) * 4;      // 0..124

    float acc[8][8];
#pragma unroll
    for (int i = 0; i < 8; i++)
#pragma unroll
        for (int j = 0; j < 8; j++) acc[i][j] = 0.0f;

    // ---- prologue: load tile k0=0 into buffer 0 ----
    {
        float4 av = make_float4(0.f, 0.f, 0.f, 0.f);
        if (row0 + a_row < M)
            av = *(const float4*)&A[(size_t)(row0 + a_row) * K + a_col];
        As[0][a_col + 0][a_row] = av.x;
        As[0][a_col + 1][a_row] = av.y;
        As[0][a_col + 2][a_row] = av.z;
        As[0][a_col + 3][a_row] = av.w;

        float4 bv = make_float4(0.f, 0.f, 0.f, 0.f);
        if (col0 + b_col < N)
            bv = *(const float4*)&B[(size_t)b_row * N + col0 + b_col];
        *(float4*)&Bs[0][b_row][b_col] = bv;
    }
    __syncthreads();

    int buf = 0;
    for (int k0 = 0; k0 < K; k0 += GBK) {
        const bool has_next = (k0 + GBK) < K;

        // ---- prefetch next tile into registers (overlaps with compute) ----
        float4 av = make_float4(0.f, 0.f, 0.f, 0.f);
        float4 bv = make_float4(0.f, 0.f, 0.f, 0.f);
        if (has_next) {
            if (row0 + a_row < M)
                av = *(const float4*)&A[(size_t)(row0 + a_row) * K + k0 + GBK + a_col];
            if (col0 + b_col < N)
                bv = *(const float4*)&B[(size_t)(k0 + GBK + b_row) * N + col0 + b_col];
        }

        // ---- compute on current buffer ----
#pragma unroll
        for (int k = 0; k < GBK; k++) {
            float a[8], b[8];
            *(float4*)&a[0] = *(float4*)&As[buf][k][tr * 8];
            *(float4*)&a[4] = *(float4*)&As[buf][k][tr * 8 + 4];
            *(float4*)&b[0] = *(float4*)&Bs[buf][k][tc * 8];
            *(float4*)&b[4] = *(float4*)&Bs[buf][k][tc * 8 + 4];
#pragma unroll
            for (int i = 0; i < 8; i++)
#pragma unroll
                for (int j = 0; j < 8; j++)
                    acc[i][j] += a[i] * b[j];
        }

        // ---- stage prefetched tile into the other buffer ----
        if (has_next) {
            As[buf ^ 1][a_col + 0][a_row] = av.x;
            As[buf ^ 1][a_col + 1][a_row] = av.y;
            As[buf ^ 1][a_col + 2][a_row] = av.z;
            As[buf ^ 1][a_col + 3][a_row] = av.w;
            *(float4*)&Bs[buf ^ 1][b_row][b_col] = bv;
        }
        __syncthreads();
        buf ^= 1;
    }

#pragma unroll
    for (int i = 0; i < 8; i++) {
        int r = row0 + tr * 8 + i;
        if (r >= M) continue;
#pragma unroll
        for (int j = 0; j < 8; j++) {
            int c = col0 + tc * 8 + j;
            if (c < N) {
                float v = acc[i][j];
                if (bias) v += bias[c];
                C[(size_t)r * N + c] = v;
            }
        }
    }
}

// ---------------- RoPE (in-place, one thread per 64-wide row) ----------------
__device__ __forceinline__ void rope_row(float* p, int t)
{
    float x1[32], x2[32];
#pragma unroll
    for (int i = 0; i < 32; i++) { x1[i] = p[i]; x2[i] = p[i + 32]; }
#pragma unroll 8
    for (int i = 0; i < 32; i++) {
        float inv = powf(10000.0f, -((float)i) / 32.0f);
        float f   = (float)t * inv;
        float s, c;
        sincosf(f, &s, &c);
        p[2 * i]     = x1[i] * c - x2[i] * s;
        p[2 * i + 1] = x1[i] * s + x2[i] * c;
    }
}

__global__ void rope_kr_kernel(float* __restrict__ kr)
{
    int row = blockIdx.x * blockDim.x + threadIdx.x;
    if (row >= MR) return;
    rope_row(kr + (size_t)row * DRr, row % Tt);
}

__global__ void rope_qr_kernel(float* __restrict__ qr)
{
    int idx = blockIdx.x * blockDim.x + threadIdx.x;
    if (idx >= MR * Hh) return;
    int bt = idx / Hh;
    int h  = idx % Hh;
    rope_row(qr + (size_t)bt * (Hh * DRr) + h * DRr, bt % Tt);
}

// ---------------- fused flash-style attention --------------------------------
// grid: (T/64, H, B), block: 256 threads.
// Qf = [Q | q_R] (192 dims), Kf = [K | k_R], softmax over all T keys, ctx = P@V.
// Scores and online-softmax state (m, l) live entirely in registers; each row's
// 64 columns are owned by one half-warp, so reductions use __shfl_xor (1..8).
#define AT_BM 64
#define AT_BN 64
#define DQF   192
#define SPAD  68      // padded stride for d-major Q/K and for the P^T tile

#define OFF_QS  0
#define OFF_KS  (OFF_QS + DQF*SPAD)        // 13056
#define OFF_VS  (OFF_KS + DQF*SPAD)        // 26112
#define OFF_PT  (OFF_VS + AT_BN*HDd)       // 34304
#define ATT_SMEM_FLOATS (OFF_PT + AT_BN*SPAD)  // 38656
#define ATT_SMEM_BYTES  (ATT_SMEM_FLOATS * 4)  // 154624

__global__ __launch_bounds__(256)
void mla_attn(const float* __restrict__ Qm, const float* __restrict__ qR,
              const float* __restrict__ Km, const float* __restrict__ kR,
              const float* __restrict__ Vm, float* __restrict__ ctx)
{
    extern __shared__ float sm[];
    float* Qs = sm + OFF_QS;    // [192][68] d-major
    float* Ks = sm + OFF_KS;    // [192][68] d-major
    float* Vs = sm + OFF_VS;    // [64][128]
    float* Pt = sm + OFF_PT;    // [64][68] exp(S), transposed: Pt[col][row]

    const int tid = threadIdx.x;
    const int q0  = blockIdx.x * AT_BM;
    const int h   = blockIdx.y;
    const int b   = blockIdx.z;

    const int tr = tid / 16;      // 0..15 (row-block; one half-warp per block)
    const int tc = tid % 16;      // 0..15 (col-block)
    const int r0 = tr * 4;        // output rows (4)
    const int c0 = tc * 4;        // score cols (4)
    const int cv0 = tc * 8;       // V cols (8)

    const float scale = rsqrtf((float)DQF);

    // ---- load Q (with scale folded in) into d-major smem ----
    for (int i = tid; i < AT_BM * (DQF / 4); i += 256) {
        int m = i / (DQF / 4);
        int q = i % (DQF / 4);
        int d = q * 4;
        int grow = b * Tt + q0 + m;
        float4 v;
        if (d < HDd) v = *(const float4*)&Qm[(size_t)grow * Dd + h * HDd + d];
        else         v = *(const float4*)&qR[(size_t)grow * (Hh * DRr) + h * DRr + (d - HDd)];
        Qs[(d + 0) * SPAD + m] = v.x * scale;
        Qs[(d + 1) * SPAD + m] = v.y * scale;
        Qs[(d + 2) * SPAD + m] = v.z * scale;
        Qs[(d + 3) * SPAD + m] = v.w * scale;
    }

    // per-thread online-softmax state for rows r0..r0+3 (replicated in half-warp)
    float m_reg[4], l_reg[4];
#pragma unroll
    for (int i = 0; i < 4; i++) { m_reg[i] = -1e30f; l_reg[i] = 0.0f; }

    float acc[4][8];
#pragma unroll
    for (int i = 0; i < 4; i++)
#pragma unroll
        for (int j = 0; j < 8; j++) acc[i][j] = 0.0f;

    __syncthreads();

    for (int k0 = 0; k0 < Tt; k0 += AT_BN) {
        // ---- load Kf tile (d-major) and V tile ----
        for (int i = tid; i < AT_BN * (DQF / 4); i += 256) {
            int n = i / (DQF / 4);
            int q = i % (DQF / 4);
            int d = q * 4;
            int grow = b * Tt + k0 + n;
            float4 v;
            if (d < HDd) v = *(const float4*)&Km[(size_t)grow * Dd + h * HDd + d];
            else         v = *(const float4*)&kR[(size_t)grow * DRr + (d - HDd)];
            Ks[(d + 0) * SPAD + n] = v.x;
            Ks[(d + 1) * SPAD + n] = v.y;
            Ks[(d + 2) * SPAD + n] = v.z;
            Ks[(d + 3) * SPAD + n] = v.w;
        }
        for (int i = tid; i < AT_BN * (HDd / 4); i += 256) {
            int n = i / (HDd / 4);
            int q = i % (HDd / 4);
            int dv = q * 4;
            *(float4*)&Vs[n * HDd + dv] =
                *(const float4*)&Vm[(size_t)(b * Tt + k0 + n) * Dd + h * HDd + dv];
        }
        __syncthreads();

        // ---- S = Qf @ Kf^T (scaled; 4x4 per thread, registers only) ----
        float sacc[4][4];
#pragma unroll
        for (int i = 0; i < 4; i++)
#pragma unroll
            for (int j = 0; j < 4; j++) sacc[i][j] = 0.0f;
#pragma unroll 8
        for (int d = 0; d < DQF; d++) {
            float4 qa = *(const float4*)&Qs[d * SPAD + r0];
            float4 kb = *(const float4*)&Ks[d * SPAD + c0];
            float qv[4] = {qa.x, qa.y, qa.z, qa.w};
            float kv[4] = {kb.x, kb.y, kb.z, kb.w};
#pragma unroll
            for (int i = 0; i < 4; i++)
#pragma unroll
                for (int j = 0; j < 4; j++)
                    sacc[i][j] += qv[i] * kv[j];
        }

        // ---- online softmax, all in registers (half-warp reductions) ----
        float rmax[4];
#pragma unroll
        for (int i = 0; i < 4; i++)
            rmax[i] = fmaxf(fmaxf(sacc[i][0], sacc[i][1]),
                            fmaxf(sacc[i][2], sacc[i][3]));
#pragma unroll
        for (int off = 1; off < 16; off <<= 1) {
#pragma unroll
            for (int i = 0; i < 4; i++)
                rmax[i] = fmaxf(rmax[i], __shfl_xor_sync(0xffffffffu, rmax[i], off));
        }

        float p[4][4], tsum[4], alpha[4];
#pragma unroll
        for (int i = 0; i < 4; i++) {
            float m_new = fmaxf(m_reg[i], rmax[i]);
            alpha[i] = __expf(m_reg[i] - m_new);
            m_reg[i] = m_new;
            float s = 0.0f;
#pragma unroll
            for (int j = 0; j < 4; j++) {
                p[i][j] = __expf(sacc[i][j] - m_new);
                s += p[i][j];
            }
            tsum[i] = s;
        }
#pragma unroll
        for (int off = 1; off < 16; off <<= 1) {
#pragma unroll
            for (int i = 0; i < 4; i++)
                tsum[i] += __shfl_xor_sync(0xffffffffu, tsum[i], off);
        }
#pragma unroll
        for (int i = 0; i < 4; i++) {
            l_reg[i] = l_reg[i] * alpha[i] + tsum[i];
#pragma unroll
            for (int j = 0; j < 8; j++) acc[i][j] *= alpha[i];
        }

        // ---- write P^T to smem (float4 per column) ----
#pragma unroll
        for (int j = 0; j < 4; j++) {
            float4 pc = make_float4(p[0][j], p[1][j], p[2][j], p[3][j]);
            *(float4*)&Pt[(c0 + j) * SPAD + r0] = pc;
        }
        __syncthreads();

        // ---- acc += P @ V ----
#pragma unroll 4
        for (int n = 0; n < AT_BN; n++) {
            float4 p4 = *(const float4*)&Pt[n * SPAD + r0];
            float pv[4] = {p4.x, p4.y, p4.z, p4.w};
            float4 v0 = *(const float4*)&Vs[n * HDd + cv0];
            float4 v1 = *(const float4*)&Vs[n * HDd + cv0 + 4];
            float vv[8] = {v0.x, v0.y, v0.z, v0.w, v1.x, v1.y, v1.z, v1.w};
#pragma unroll
            for (int i = 0; i < 4; i++)
#pragma unroll
                for (int j = 0; j < 8; j++)
                    acc[i][j] += pv[i] * vv[j];
        }
        __syncthreads();
    }

    // ---- epilogue: normalize and write ctx[b, t, h*128 + dv] ----
#pragma unroll
    for (int i = 0; i < 4; i++) {
        float inv = 1.0f / l_reg[i];
        int grow = b * Tt + q0 + r0 + i;
        float4 o0 = make_float4(acc[i][0] * inv, acc[i][1] * inv,
                                acc[i][2] * inv, acc[i][3] * inv);
        float4 o1 = make_float4(acc[i][4] * inv, acc[i][5] * inv,
                                acc[i][6] * inv, acc[i][7] * inv);
        *(float4*)&ctx[(size_t)grow * Dd + h * HDd + cv0]     = o0;
        *(float4*)&ctx[(size_t)grow * Dd + h * HDd + cv0 + 4] = o1;
    }
}

// ---------------- host driver ------------------------------------------------
static inline void launch_sgemm(const float* A, const float* B, float* C,
                                int M, int N, int K, const float* bias)
{
    dim3 grid((N + GBN - 1) / GBN, (M + GBM - 1) / GBM);
    sgemm_kernel<<<grid, 256>>>(A, B, C, M, N, K, bias);
}

extern "C" void kernel_launch(void* const* d_in, const int* in_sizes, int n_in,
                              void* d_out, int out_size)
{
    const float* x     = (const float*)d_in[0];
    const float* W_DKV = (const float*)d_in[1];
    const float* W_DQ  = (const float*)d_in[2];
    const float* W_UK  = (const float*)d_in[3];
    const float* W_UV  = (const float*)d_in[4];
    const float* W_UQ  = (const float*)d_in[5];
    const float* W_KR  = (const float*)d_in[6];
    const float* W_QR  = (const float*)d_in[7];
    const float* W_O   = (const float*)d_in[8];
    const float* b_O   = (const float*)d_in[9];
    float* out = (float*)d_out;

    float *ckv, *cq, *Kp, *Vp, *Qp, *krp, *qrp, *ctxp;
    cudaGetSymbolAddress((void**)&ckv,  g_ckv);
    cudaGetSymbolAddress((void**)&cq,   g_cq);
    cudaGetSymbolAddress((void**)&Kp,   g_K);
    cudaGetSymbolAddress((void**)&Vp,   g_V);
    cudaGetSymbolAddress((void**)&Qp,   g_Q);
    cudaGetSymbolAddress((void**)&krp,  g_kr);
    cudaGetSymbolAddress((void**)&qrp,  g_qr);
    cudaGetSymbolAddress((void**)&ctxp, g_ctx);

    // down-projections + rope key
    launch_sgemm(x, W_DKV, ckv, MR, DCc, Dd, nullptr);
    launch_sgemm(x, W_DQ,  cq,  MR, DCc, Dd, nullptr);
    launch_sgemm(x, W_KR,  krp, MR, DRr, Dd, nullptr);
    rope_kr_kernel<<<(MR + 127) / 128, 128>>>(krp);

    // up-projections
    launch_sgemm(ckv, W_UK, Kp,  MR, Dd,        DCc, nullptr);
    launch_sgemm(ckv, W_UV, Vp,  MR, Dd,        DCc, nullptr);
    launch_sgemm(cq,  W_UQ, Qp,  MR, Dd,        DCc, nullptr);
    launch_sgemm(cq,  W_QR, qrp, MR, Hh * DRr,  DCc, nullptr);
    rope_qr_kernel<<<(MR * Hh + 127) / 128, 128>>>(qrp);

    // fused attention
    cudaFuncSetAttribute(mla_attn, cudaFuncAttributeMaxDynamicSharedMemorySize,
                         ATT_SMEM_BYTES);
    mla_attn<<<dim3(Tt / AT_BM, Hh, Bb), 256, ATT_SMEM_BYTES>>>(Qp, qrp, Kp, krp, Vp, ctxp);

    // output projection + bias
    launch_sgemm(ctxp, W_O, out, MR, Dd, Dd, b_O);
}

// round 8
// speedup vs baseline: 2.4035x; 2.4035x over previous
#include <cuda_runtime.h>
#include <cuda_bf16.h>
#include <math.h>

// Problem constants
#define Bb   2
#define Tt   2048
#define Dd   2048
#define Hh   16
#define HDd  128
#define DCc  512
#define DRr  64
#define MR   (Bb*Tt)          // 4096 rows

// ---------------- fp32 scratch ------------------------------------------------
__device__ float g_ckv[MR*DCc];
__device__ float g_cq [MR*DCc];
__device__ float g_K  [MR*Dd];
__device__ float g_V  [MR*Dd];
__device__ float g_Q  [MR*Dd];
__device__ float g_kr [MR*DRr];
__device__ float g_qr [MR*Hh*DRr];
__device__ float g_ctx[MR*Dd];

// ---------------- bf16 hi/lo scratch (activations: row-major [M][K]) ----------
__device__ __nv_bfloat16 g_xh  [MR*Dd],  g_xl  [MR*Dd];
__device__ __nv_bfloat16 g_ckvh[MR*DCc], g_ckvl[MR*DCc];
__device__ __nv_bfloat16 g_cqh [MR*DCc], g_cql [MR*DCc];
__device__ __nv_bfloat16 g_ctxh[MR*Dd],  g_ctxl[MR*Dd];

// ---------------- bf16 hi/lo weights, TRANSPOSED to [N][K] --------------------
__device__ __nv_bfloat16 g_WDKVh[DCc*Dd],       g_WDKVl[DCc*Dd];
__device__ __nv_bfloat16 g_WDQh [DCc*Dd],       g_WDQl [DCc*Dd];
__device__ __nv_bfloat16 g_WUKh [Dd*DCc],       g_WUKl [Dd*DCc];
__device__ __nv_bfloat16 g_WUVh [Dd*DCc],       g_WUVl [Dd*DCc];
__device__ __nv_bfloat16 g_WUQh [Dd*DCc],       g_WUQl [Dd*DCc];
__device__ __nv_bfloat16 g_WKRh [DRr*Dd],       g_WKRl [DRr*Dd];
__device__ __nv_bfloat16 g_WQRh [Hh*DRr*DCc],   g_WQRl [Hh*DRr*DCc];
__device__ __nv_bfloat16 g_WOh  [Dd*Dd],        g_WOl  [Dd*Dd];

// ---------------- attention staging buffers (bf16 hi/lo) ----------------------
// Qf/Kf: [b][h][t][192], Vt: [b][h][d=128][t]
#define QF_ELEMS (Bb*Hh*Tt*192)
#define VT_ELEMS (Bb*Hh*HDd*Tt)
__device__ __nv_bfloat16 g_QfH[QF_ELEMS], g_QfL[QF_ELEMS];
__device__ __nv_bfloat16 g_KfH[QF_ELEMS], g_KfL[QF_ELEMS];
__device__ __nv_bfloat16 g_VtH[VT_ELEMS], g_VtL[VT_ELEMS];

// ---------------- split: fp32 -> (hi, lo) bf16, same layout -------------------
__global__ void split_kernel(const float* __restrict__ in,
                             __nv_bfloat16* __restrict__ hi,
                             __nv_bfloat16* __restrict__ lo, int n4)
{
    int i = blockIdx.x * 256 + threadIdx.x;
    if (i >= n4) return;
    float4 v = ((const float4*)in)[i];
    __nv_bfloat16 h0 = __float2bfloat16(v.x);
    __nv_bfloat16 h1 = __float2bfloat16(v.y);
    __nv_bfloat16 h2 = __float2bfloat16(v.z);
    __nv_bfloat16 h3 = __float2bfloat16(v.w);
    __nv_bfloat16 l0 = __float2bfloat16(v.x - __bfloat162float(h0));
    __nv_bfloat16 l1 = __float2bfloat16(v.y - __bfloat162float(h1));
    __nv_bfloat16 l2 = __float2bfloat16(v.z - __bfloat162float(h2));
    __nv_bfloat16 l3 = __float2bfloat16(v.w - __bfloat162float(h3));
    ((__nv_bfloat162*)hi)[2*i]   = __halves2bfloat162(h0, h1);
    ((__nv_bfloat162*)hi)[2*i+1] = __halves2bfloat162(h2, h3);
    ((__nv_bfloat162*)lo)[2*i]   = __halves2bfloat162(l0, l1);
    ((__nv_bfloat162*)lo)[2*i+1] = __halves2bfloat162(l2, l3);
}

// ---------------- split + transpose: fp32 [R][C] -> (hi, lo) bf16 [C][R] ------
__global__ void splitT_kernel(const float* __restrict__ in,
                              __nv_bfloat16* __restrict__ hT,
                              __nv_bfloat16* __restrict__ lT, int R, int C)
{
    __shared__ float t[32][33];
    int bx = blockIdx.x, by = blockIdx.y;
    int tx = threadIdx.x, ty = threadIdx.y;   // 32 x 8
#pragma unroll
    for (int i = 0; i < 32; i += 8)
        t[ty + i][tx] = in[(size_t)(by*32 + ty + i)*C + bx*32 + tx];
    __syncthreads();
#pragma unroll
    for (int i = 0; i < 32; i += 8) {
        float v = t[tx][ty + i];
        int r = bx*32 + ty + i;
        int c = by*32 + tx;
        __nv_bfloat16 h = __float2bfloat16(v);
        hT[(size_t)r*R + c] = h;
        lT[(size_t)r*R + c] = __float2bfloat16(v - __bfloat162float(h));
    }
}

// ---------------- bf16x3 tensor-core GEMM (unchanged, audited) -----------------
#define TBM 128
#define TBN 128
#define TBK 32
#define TKP 40
#define SBUF 20480
#define GEMM_SMEM_BYTES (2*SBUF*2)

__device__ __forceinline__ void mma16816(float* d, const unsigned* a, const unsigned* b)
{
    asm volatile(
        "mma.sync.aligned.m16n8k16.row.col.f32.bf16.bf16.f32 "
        "{%0,%1,%2,%3}, {%4,%5,%6,%7}, {%8,%9}, {%0,%1,%2,%3};"
        : "+f"(d[0]), "+f"(d[1]), "+f"(d[2]), "+f"(d[3])
        : "r"(a[0]), "r"(a[1]), "r"(a[2]), "r"(a[3]),
          "r"(b[0]), "r"(b[1]));
}

__global__ __launch_bounds__(256)
void mma_gemm(const __nv_bfloat16* __restrict__ Ah, const __nv_bfloat16* __restrict__ Al,
              const __nv_bfloat16* __restrict__ Bh, const __nv_bfloat16* __restrict__ Bl,
              float* __restrict__ C, int M, int N, int K,
              const float* __restrict__ bias)
{
    extern __shared__ __nv_bfloat16 sb[];
    const int tid  = threadIdx.x;
    const int lane = tid & 31;
    const int warp = tid >> 5;
    const int wm = warp & 3;
    const int wn = warp >> 2;
    const int row0 = blockIdx.y * TBM;
    const int col0 = blockIdx.x * TBN;

    const int ldr = tid >> 3;
    const int ldc = (tid & 7) * 4;

    float acc[2][8][4];
#pragma unroll
    for (int i = 0; i < 2; i++)
#pragma unroll
        for (int j = 0; j < 8; j++)
#pragma unroll
            for (int r = 0; r < 4; r++) acc[i][j][r] = 0.0f;

    uint2 pah[4], pal[4], pbh[4], pbl[4];

    auto load_tile = [&](int k0) {
#pragma unroll
        for (int p = 0; p < 4; p++) {
            int row = p*32 + ldr;
            size_t aoff = (size_t)(row0 + row) * K + k0 + ldc;
            pah[p] = *(const uint2*)(Ah + aoff);
            pal[p] = *(const uint2*)(Al + aoff);
            if (col0 + row < N) {
                size_t boff = (size_t)(col0 + row) * K + k0 + ldc;
                pbh[p] = *(const uint2*)(Bh + boff);
                pbl[p] = *(const uint2*)(Bl + boff);
            } else {
                pbh[p] = make_uint2(0u, 0u);
                pbl[p] = make_uint2(0u, 0u);
            }
        }
    };
    auto store_tile = [&](int buf) {
        __nv_bfloat16* base = sb + buf * SBUF;
#pragma unroll
        for (int p = 0; p < 4; p++) {
            int row = p*32 + ldr;
            int off = row * TKP + ldc;
            *(uint2*)(base + off)         = pah[p];
            *(uint2*)(base + 5120 + off)  = pal[p];
            *(uint2*)(base + 10240 + off) = pbh[p];
            *(uint2*)(base + 15360 + off) = pbl[p];
        }
    };

    load_tile(0);
    store_tile(0);
    __syncthreads();

    int buf = 0;
    const int a_r = lane >> 2;
    const int a_k = (lane & 3) << 1;

    for (int k0 = 0; k0 < K; k0 += TBK) {
        const bool has_next = (k0 + TBK) < K;
        if (has_next) load_tile(k0 + TBK);

        const __nv_bfloat16* base = sb + buf * SBUF;
#pragma unroll
        for (int kk = 0; kk < TBK; kk += 16) {
            unsigned ah[2][4], al[2][4], bh[8][2], bl[8][2];
#pragma unroll
            for (int i = 0; i < 2; i++) {
#pragma unroll
                for (int r = 0; r < 4; r++) {
                    int rr = wm*32 + i*16 + a_r + ((r & 1) << 3);
                    int cc = kk + a_k + ((r >> 1) << 3);
                    ah[i][r] = *(const unsigned*)(base + rr*TKP + cc);
                    al[i][r] = *(const unsigned*)(base + 5120 + rr*TKP + cc);
                }
            }
#pragma unroll
            for (int j = 0; j < 8; j++) {
#pragma unroll
                for (int r = 0; r < 2; r++) {
                    int nn = wn*64 + j*8 + a_r;
                    int cc = kk + a_k + (r << 3);
                    bh[j][r] = *(const unsigned*)(base + 10240 + nn*TKP + cc);
                    bl[j][r] = *(const unsigned*)(base + 15360 + nn*TKP + cc);
                }
            }
#pragma unroll
            for (int i = 0; i < 2; i++)
#pragma unroll
                for (int j = 0; j < 8; j++) {
                    mma16816(acc[i][j], ah[i], bh[j]);
                    mma16816(acc[i][j], ah[i], bl[j]);
                    mma16816(acc[i][j], al[i], bh[j]);
                }
        }

        if (has_next) store_tile(buf ^ 1);
        __syncthreads();
        buf ^= 1;
    }

#pragma unroll
    for (int i = 0; i < 2; i++) {
        int r_ = row0 + wm*32 + i*16 + (lane >> 2);
#pragma unroll
        for (int j = 0; j < 8; j++) {
            int c_ = col0 + wn*64 + j*8 + ((lane & 3) << 1);
            if (c_ < N) {
                float b0 = bias ? bias[c_]     : 0.0f;
                float b1 = bias ? bias[c_ + 1] : 0.0f;
                float2 v0 = make_float2(acc[i][j][0] + b0, acc[i][j][1] + b1);
                float2 v1 = make_float2(acc[i][j][2] + b0, acc[i][j][3] + b1);
                *(float2*)&C[(size_t)r_ * N + c_]       = v0;
                *(float2*)&C[(size_t)(r_ + 8) * N + c_] = v1;
            }
        }
    }
}

// ---------------- RoPE (unchanged) ---------------------------------------------
__device__ __forceinline__ void rope_row(float* p, int t)
{
    float x1[32], x2[32];
#pragma unroll
    for (int i = 0; i < 32; i++) { x1[i] = p[i]; x2[i] = p[i + 32]; }
#pragma unroll 8
    for (int i = 0; i < 32; i++) {
        float inv = powf(10000.0f, -((float)i) / 32.0f);
        float f   = (float)t * inv;
        float s, c;
        sincosf(f, &s, &c);
        p[2 * i]     = x1[i] * c - x2[i] * s;
        p[2 * i + 1] = x1[i] * s + x2[i] * c;
    }
}

__global__ void rope_kr_kernel(float* __restrict__ kr)
{
    int row = blockIdx.x * blockDim.x + threadIdx.x;
    if (row >= MR) return;
    rope_row(kr + (size_t)row * DRr, row % Tt);
}

__global__ void rope_qr_kernel(float* __restrict__ qr)
{
    int idx = blockIdx.x * blockDim.x + threadIdx.x;
    if (idx >= MR * Hh) return;
    int bt = idx / Hh;
    int h  = idx % Hh;
    rope_row(qr + (size_t)bt * (Hh * DRr) + h * DRr, bt % Tt);
}

// ---------------- attention prep: build Qf/Kf [b][h][t][192] hi/lo -------------
__device__ __forceinline__ void split_store4(float4 v, __nv_bfloat16* H,
                                             __nv_bfloat16* L, size_t o)
{
    __nv_bfloat16 h0 = __float2bfloat16(v.x);
    __nv_bfloat16 h1 = __float2bfloat16(v.y);
    __nv_bfloat16 h2 = __float2bfloat16(v.z);
    __nv_bfloat16 h3 = __float2bfloat16(v.w);
    ((__nv_bfloat162*)(H + o))[0] = __halves2bfloat162(h0, h1);
    ((__nv_bfloat162*)(H + o))[1] = __halves2bfloat162(h2, h3);
    ((__nv_bfloat162*)(L + o))[0] = __halves2bfloat162(
        __float2bfloat16(v.x - __bfloat162float(h0)),
        __float2bfloat16(v.y - __bfloat162float(h1)));
    ((__nv_bfloat162*)(L + o))[1] = __halves2bfloat162(
        __float2bfloat16(v.z - __bfloat162float(h2)),
        __float2bfloat16(v.w - __bfloat162float(h3)));
}

__global__ void prep_qk_kernel(const float* __restrict__ Q, const float* __restrict__ qr,
                               const float* __restrict__ K, const float* __restrict__ kr,
                               __nv_bfloat16* __restrict__ QfH, __nv_bfloat16* __restrict__ QfL,
                               __nv_bfloat16* __restrict__ KfH, __nv_bfloat16* __restrict__ KfL)
{
    int idx = blockIdx.x * 256 + threadIdx.x;          // over B*H*T*48
    if (idx >= Bb*Hh*Tt*48) return;
    int d4 = idx % 48;
    int t_ = (idx / 48) % Tt;
    int h  = (idx / (48*Tt)) % Hh;
    int b  =  idx / (48*Tt*Hh);
    int d  = d4 * 4;
    int bt = b*Tt + t_;
    const float scale = rsqrtf(192.0f);

    float4 qv, kv;
    if (d < HDd) {
        qv = *(const float4*)&Q[(size_t)bt*Dd + h*HDd + d];
        kv = *(const float4*)&K[(size_t)bt*Dd + h*HDd + d];
    } else {
        qv = *(const float4*)&qr[(size_t)bt*(Hh*DRr) + h*DRr + (d - HDd)];
        kv = *(const float4*)&kr[(size_t)bt*DRr + (d - HDd)];
    }
    qv.x *= scale; qv.y *= scale; qv.z *= scale; qv.w *= scale;

    size_t o = ((size_t)(b*Hh + h)*Tt + t_)*192 + d;
    split_store4(qv, QfH, QfL, o);
    split_store4(kv, KfH, KfL, o);
}

// ---------------- attention prep: V transposed to [b][h][d][t] hi/lo -----------
__global__ void prep_vt_kernel(const float* __restrict__ V,
                               __nv_bfloat16* __restrict__ VtH,
                               __nv_bfloat16* __restrict__ VtL)
{
    __shared__ float t[32][33];
    int t0 = blockIdx.x * 32;
    int d0 = blockIdx.y * 32;
    int bh = blockIdx.z;
    int b = bh / Hh, h = bh % Hh;
    int tx = threadIdx.x, ty = threadIdx.y;   // 32 x 8
#pragma unroll
    for (int i = 0; i < 32; i += 8)
        t[ty + i][tx] = V[(size_t)(b*Tt + t0 + ty + i)*Dd + h*HDd + d0 + tx];
    __syncthreads();
#pragma unroll
    for (int i = 0; i < 32; i += 8) {
        float v = t[tx][ty + i];
        size_t o = ((size_t)bh*HDd + d0 + ty + i)*Tt + t0 + tx;
        __nv_bfloat16 hh = __float2bfloat16(v);
        VtH[o] = hh;
        VtL[o] = __float2bfloat16(v - __bfloat162float(hh));
    }
}

// ---------------- bf16x3 tensor-core flash attention ---------------------------
// Block: 128 q-rows, 8 warps (16 rows each, warp-local softmax), key tiles of 64.
#define FBM 128
#define FBN 64
#define QK_STR 200       // padded stride for 192-dim rows (bf16 units)
#define V_STR  72        // padded stride for 64-key rows
#define O_QH 0
#define O_QL (O_QH + FBM*QK_STR)          // 25600
#define O_KH (O_QL + FBM*QK_STR)          // 51200
#define O_KL (O_KH + FBN*QK_STR)          // 64000
#define O_VH (O_KL + FBN*QK_STR)          // 76800
#define O_VL (O_VH + HDd*V_STR)           // 86016
#define FATT_SMEM_BF16 (O_VL + HDd*V_STR) // 95232
#define FATT_SMEM_BYTES (FATT_SMEM_BF16*2)// 190464

__device__ __forceinline__ void split2(float a, float b, unsigned& hi, unsigned& lo)
{
    __nv_bfloat16 ha = __float2bfloat16(a), hb = __float2bfloat16(b);
    __nv_bfloat16 la = __float2bfloat16(a - __bfloat162float(ha));
    __nv_bfloat16 lb = __float2bfloat16(b - __bfloat162float(hb));
    hi = (unsigned)__bfloat16_as_ushort(ha) | ((unsigned)__bfloat16_as_ushort(hb) << 16);
    lo = (unsigned)__bfloat16_as_ushort(la) | ((unsigned)__bfloat16_as_ushort(lb) << 16);
}

__global__ __launch_bounds__(256)
void mla_attn_mma(const __nv_bfloat16* __restrict__ QfH, const __nv_bfloat16* __restrict__ QfL,
                  const __nv_bfloat16* __restrict__ KfH, const __nv_bfloat16* __restrict__ KfL,
                  const __nv_bfloat16* __restrict__ VtH, const __nv_bfloat16* __restrict__ VtL,
                  float* __restrict__ ctx)
{
    extern __shared__ __nv_bfloat16 sm2[];
    const int tid  = threadIdx.x;
    const int lane = tid & 31;
    const int warp = tid >> 5;
    const int q0 = blockIdx.x * FBM;
    const int h  = blockIdx.y;
    const int b  = blockIdx.z;
    const int bh = b*Hh + h;
    const int a_r = lane >> 2;
    const int a_k = (lane & 3) << 1;

    // ---- load Q tile (hi+lo) into smem, uint4 = 8 bf16 ----
    for (int i = tid; i < FBM*24; i += 256) {
        int row = i / 24, u = (i % 24) * 8;
        size_t g = ((size_t)bh*Tt + q0 + row)*192 + u;
        *(uint4*)(sm2 + O_QH + row*QK_STR + u) = *(const uint4*)(QfH + g);
        *(uint4*)(sm2 + O_QL + row*QK_STR + u) = *(const uint4*)(QfL + g);
    }

    float m0 = -1e30f, m1 = -1e30f, l0 = 0.0f, l1 = 0.0f;
    float acc[16][4];
#pragma unroll
    for (int j = 0; j < 16; j++)
#pragma unroll
        for (int r = 0; r < 4; r++) acc[j][r] = 0.0f;

    for (int k0 = 0; k0 < Tt; k0 += FBN) {
        __syncthreads();   // previous iteration's smem reads complete
        // ---- load K tile (hi+lo) and V tile (hi+lo, d-major) ----
        for (int i = tid; i < FBN*24; i += 256) {
            int row = i / 24, u = (i % 24) * 8;
            size_t g = ((size_t)bh*Tt + k0 + row)*192 + u;
            *(uint4*)(sm2 + O_KH + row*QK_STR + u) = *(const uint4*)(KfH + g);
            *(uint4*)(sm2 + O_KL + row*QK_STR + u) = *(const uint4*)(KfL + g);
        }
        for (int i = tid; i < HDd*8; i += 256) {
            int row = i / 8, u = (i % 8) * 8;
            size_t g = ((size_t)bh*HDd + row)*Tt + k0 + u;
            *(uint4*)(sm2 + O_VH + row*V_STR + u) = *(const uint4*)(VtH + g);
            *(uint4*)(sm2 + O_VL + row*V_STR + u) = *(const uint4*)(VtL + g);
        }
        __syncthreads();

        // ---- S = Qf @ Kf^T  (warp: 16 rows x 64 keys, bf16x3) ----
        float sacc[8][4];
#pragma unroll
        for (int j = 0; j < 8; j++)
#pragma unroll
            for (int r = 0; r < 4; r++) sacc[j][r] = 0.0f;

        for (int kk = 0; kk < 192; kk += 16) {
            unsigned ah[4], al[4];
#pragma unroll
            for (int r = 0; r < 4; r++) {
                int rr = warp*16 + a_r + ((r & 1) << 3);
                int cc = kk + a_k + ((r >> 1) << 3);
                ah[r] = *(const unsigned*)(sm2 + O_QH + rr*QK_STR + cc);
                al[r] = *(const unsigned*)(sm2 + O_QL + rr*QK_STR + cc);
            }
#pragma unroll
            for (int j = 0; j < 8; j++) {
                unsigned kb[2], kl[2];
#pragma unroll
                for (int r = 0; r < 2; r++) {
                    int nn = j*8 + a_r;
                    int cc = kk + a_k + (r << 3);
                    kb[r] = *(const unsigned*)(sm2 + O_KH + nn*QK_STR + cc);
                    kl[r] = *(const unsigned*)(sm2 + O_KL + nn*QK_STR + cc);
                }
                mma16816(sacc[j], ah, kb);
                mma16816(sacc[j], ah, kl);
                mma16816(sacc[j], al, kb);
            }
        }

        // ---- warp-local online softmax (rows g=a_r and g+8) ----
        float mx0 = -1e30f, mx1 = -1e30f;
#pragma unroll
        for (int j = 0; j < 8; j++) {
            mx0 = fmaxf(mx0, fmaxf(sacc[j][0], sacc[j][1]));
            mx1 = fmaxf(mx1, fmaxf(sacc[j][2], sacc[j][3]));
        }
        mx0 = fmaxf(mx0, __shfl_xor_sync(0xffffffffu, mx0, 1));
        mx0 = fmaxf(mx0, __shfl_xor_sync(0xffffffffu, mx0, 2));
        mx1 = fmaxf(mx1, __shfl_xor_sync(0xffffffffu, mx1, 1));
        mx1 = fmaxf(mx1, __shfl_xor_sync(0xffffffffu, mx1, 2));

        float mn0 = fmaxf(m0, mx0), mn1 = fmaxf(m1, mx1);
        float al0 = __expf(m0 - mn0), al1 = __expf(m1 - mn1);
        m0 = mn0; m1 = mn1;

        float s0 = 0.0f, s1 = 0.0f;
#pragma unroll
        for (int j = 0; j < 8; j++) {
            sacc[j][0] = __expf(sacc[j][0] - mn0); s0 += sacc[j][0];
            sacc[j][1] = __expf(sacc[j][1] - mn0); s0 += sacc[j][1];
            sacc[j][2] = __expf(sacc[j][2] - mn1); s1 += sacc[j][2];
            sacc[j][3] = __expf(sacc[j][3] - mn1); s1 += sacc[j][3];
        }
        s0 += __shfl_xor_sync(0xffffffffu, s0, 1);
        s0 += __shfl_xor_sync(0xffffffffu, s0, 2);
        s1 += __shfl_xor_sync(0xffffffffu, s1, 1);
        s1 += __shfl_xor_sync(0xffffffffu, s1, 2);
        l0 = l0*al0 + s0;
        l1 = l1*al1 + s1;

#pragma unroll
        for (int j = 0; j < 16; j++) {
            acc[j][0] *= al0; acc[j][1] *= al0;
            acc[j][2] *= al1; acc[j][3] *= al1;
        }

        // ---- acc += P @ V  (P split hi/lo; fragment identity c->a) ----
#pragma unroll
        for (int c = 0; c < 4; c++) {
            unsigned pah[4], pal[4];
            split2(sacc[2*c][0],   sacc[2*c][1],   pah[0], pal[0]);
            split2(sacc[2*c][2],   sacc[2*c][3],   pah[1], pal[1]);
            split2(sacc[2*c+1][0], sacc[2*c+1][1], pah[2], pal[2]);
            split2(sacc[2*c+1][2], sacc[2*c+1][3], pah[3], pal[3]);
#pragma unroll
            for (int j2 = 0; j2 < 16; j2++) {
                unsigned vh[2], vl[2];
#pragma unroll
                for (int r = 0; r < 2; r++) {
                    int nn = j2*8 + a_r;
                    int cc = c*16 + a_k + (r << 3);
                    vh[r] = *(const unsigned*)(sm2 + O_VH + nn*V_STR + cc);
                    vl[r] = *(const unsigned*)(sm2 + O_VL + nn*V_STR + cc);
                }
                mma16816(acc[j2], pah, vh);
                mma16816(acc[j2], pah, vl);
                mma16816(acc[j2], pal, vh);
            }
        }
    }

    // ---- epilogue: normalize, write ctx[b, t, h*128 + d] ----
    float i0 = 1.0f / l0, i1 = 1.0f / l1;
    int gr = b*Tt + q0 + warp*16 + a_r;
#pragma unroll
    for (int j2 = 0; j2 < 16; j2++) {
        int col = h*HDd + j2*8 + a_k;
        *(float2*)&ctx[(size_t)gr*Dd + col] =
            make_float2(acc[j2][0]*i0, acc[j2][1]*i0);
        *(float2*)&ctx[(size_t)(gr+8)*Dd + col] =
            make_float2(acc[j2][2]*i1, acc[j2][3]*i1);
    }
}

// ---------------- host driver ---------------------------------------------------
static inline void launch_mma(const __nv_bfloat16* Ah, const __nv_bfloat16* Al,
                              const __nv_bfloat16* Bh, const __nv_bfloat16* Bl,
                              float* C, int M, int N, int K, const float* bias)
{
    dim3 grid((N + TBN - 1) / TBN, M / TBM);
    mma_gemm<<<grid, 256, GEMM_SMEM_BYTES>>>(Ah, Al, Bh, Bl, C, M, N, K, bias);
}

static inline void launch_split(const float* in, __nv_bfloat16* hi, __nv_bfloat16* lo, int n)
{
    int n4 = n / 4;
    split_kernel<<<(n4 + 255) / 256, 256>>>(in, hi, lo, n4);
}

static inline void launch_splitT(const float* in, __nv_bfloat16* hT, __nv_bfloat16* lT,
                                 int R, int C)
{
    dim3 grid(C / 32, R / 32);
    splitT_kernel<<<grid, dim3(32, 8)>>>(in, hT, lT, R, C);
}

extern "C" void kernel_launch(void* const* d_in, const int* in_sizes, int n_in,
                              void* d_out, int out_size)
{
    const float* x     = (const float*)d_in[0];
    const float* W_DKV = (const float*)d_in[1];
    const float* W_DQ  = (const float*)d_in[2];
    const float* W_UK  = (const float*)d_in[3];
    const float* W_UV  = (const float*)d_in[4];
    const float* W_UQ  = (const float*)d_in[5];
    const float* W_KR  = (const float*)d_in[6];
    const float* W_QR  = (const float*)d_in[7];
    const float* W_O   = (const float*)d_in[8];
    const float* b_O   = (const float*)d_in[9];
    float* out = (float*)d_out;

    float *ckv, *cq, *Kp, *Vp, *Qp, *krp, *qrp, *ctxp;
    cudaGetSymbolAddress((void**)&ckv,  g_ckv);
    cudaGetSymbolAddress((void**)&cq,   g_cq);
    cudaGetSymbolAddress((void**)&Kp,   g_K);
    cudaGetSymbolAddress((void**)&Vp,   g_V);
    cudaGetSymbolAddress((void**)&Qp,   g_Q);
    cudaGetSymbolAddress((void**)&krp,  g_kr);
    cudaGetSymbolAddress((void**)&qrp,  g_qr);
    cudaGetSymbolAddress((void**)&ctxp, g_ctx);

    __nv_bfloat16 *xh, *xl, *ckvh, *ckvl, *cqh, *cql, *ctxh, *ctxl;
    cudaGetSymbolAddress((void**)&xh,   g_xh);   cudaGetSymbolAddress((void**)&xl,   g_xl);
    cudaGetSymbolAddress((void**)&ckvh, g_ckvh); cudaGetSymbolAddress((void**)&ckvl, g_ckvl);
    cudaGetSymbolAddress((void**)&cqh,  g_cqh);  cudaGetSymbolAddress((void**)&cql,  g_cql);
    cudaGetSymbolAddress((void**)&ctxh, g_ctxh); cudaGetSymbolAddress((void**)&ctxl, g_ctxl);

    __nv_bfloat16 *wdkvh, *wdkvl, *wdqh, *wdql, *wukh, *wukl, *wuvh, *wuvl,
                  *wuqh, *wuql, *wkrh, *wkrl, *wqrh, *wqrl, *woh, *wol;
    cudaGetSymbolAddress((void**)&wdkvh, g_WDKVh); cudaGetSymbolAddress((void**)&wdkvl, g_WDKVl);
    cudaGetSymbolAddress((void**)&wdqh,  g_WDQh);  cudaGetSymbolAddress((void**)&wdql,  g_WDQl);
    cudaGetSymbolAddress((void**)&wukh,  g_WUKh);  cudaGetSymbolAddress((void**)&wukl,  g_WUKl);
    cudaGetSymbolAddress((void**)&wuvh,  g_WUVh);  cudaGetSymbolAddress((void**)&wuvl,  g_WUVl);
    cudaGetSymbolAddress((void**)&wuqh,  g_WUQh);  cudaGetSymbolAddress((void**)&wuql,  g_WUQl);
    cudaGetSymbolAddress((void**)&wkrh,  g_WKRh);  cudaGetSymbolAddress((void**)&wkrl,  g_WKRl);
    cudaGetSymbolAddress((void**)&wqrh,  g_WQRh);  cudaGetSymbolAddress((void**)&wqrl,  g_WQRl);
    cudaGetSymbolAddress((void**)&woh,   g_WOh);   cudaGetSymbolAddress((void**)&wol,   g_WOl);

    __nv_bfloat16 *qfh, *qfl, *kfh, *kfl, *vth, *vtl;
    cudaGetSymbolAddress((void**)&qfh, g_QfH); cudaGetSymbolAddress((void**)&qfl, g_QfL);
    cudaGetSymbolAddress((void**)&kfh, g_KfH); cudaGetSymbolAddress((void**)&kfl, g_KfL);
    cudaGetSymbolAddress((void**)&vth, g_VtH); cudaGetSymbolAddress((void**)&vtl, g_VtL);

    cudaFuncSetAttribute(mma_gemm, cudaFuncAttributeMaxDynamicSharedMemorySize,
                         GEMM_SMEM_BYTES);
    cudaFuncSetAttribute(mla_attn_mma, cudaFuncAttributeMaxDynamicSharedMemorySize,
                         FATT_SMEM_BYTES);

    // ---- split inputs / weights (weights transposed to [N][K]) ----
    launch_split(x, xh, xl, MR * Dd);
    launch_splitT(W_DKV, wdkvh, wdkvl, Dd, DCc);
    launch_splitT(W_DQ,  wdqh,  wdql,  Dd, DCc);
    launch_splitT(W_UK,  wukh,  wukl,  DCc, Dd);
    launch_splitT(W_UV,  wuvh,  wuvl,  DCc, Dd);
    launch_splitT(W_UQ,  wuqh,  wuql,  DCc, Dd);
    launch_splitT(W_KR,  wkrh,  wkrl,  Dd, DRr);
    launch_splitT(W_QR,  wqrh,  wqrl,  DCc, Hh * DRr);
    launch_splitT(W_O,   woh,   wol,   Dd, Dd);

    // ---- down-projections + rope key ----
    launch_mma(xh, xl, wdkvh, wdkvl, ckv, MR, DCc, Dd, nullptr);
    launch_mma(xh, xl, wdqh,  wdql,  cq,  MR, DCc, Dd, nullptr);
    launch_mma(xh, xl, wkrh,  wkrl,  krp, MR, DRr, Dd, nullptr);
    rope_kr_kernel<<<(MR + 127) / 128, 128>>>(krp);

    // ---- split latents ----
    launch_split(ckv, ckvh, ckvl, MR * DCc);
    launch_split(cq,  cqh,  cql,  MR * DCc);

    // ---- up-projections ----
    launch_mma(ckvh, ckvl, wukh, wukl, Kp,  MR, Dd,       DCc, nullptr);
    launch_mma(ckvh, ckvl, wuvh, wuvl, Vp,  MR, Dd,       DCc, nullptr);
    launch_mma(cqh,  cql,  wuqh, wuql, Qp,  MR, Dd,       DCc, nullptr);
    launch_mma(cqh,  cql,  wqrh, wqrl, qrp, MR, Hh * DRr, DCc, nullptr);
    rope_qr_kernel<<<(MR * Hh + 127) / 128, 128>>>(qrp);

    // ---- stage attention operands (scaled Q, Kf, V^T; hi/lo bf16) ----
    prep_qk_kernel<<<(Bb*Hh*Tt*48 + 255) / 256, 256>>>(Qp, qrp, Kp, krp,
                                                       qfh, qfl, kfh, kfl);
    prep_vt_kernel<<<dim3(Tt/32, HDd/32, Bb*Hh), dim3(32, 8)>>>(Vp, vth, vtl);

    // ---- tensor-core flash attention ----
    mla_attn_mma<<<dim3(Tt/FBM, Hh, Bb), 256, FATT_SMEM_BYTES>>>(
        qfh, qfl, kfh, kfl, vth, vtl, ctxp);

    // ---- output projection + bias ----
    launch_split(ctxp, ctxh, ctxl, MR * Dd);
    launch_mma(ctxh, ctxl, woh, wol, out, MR, Dd, Dd, b_O);
}

// round 13
// speedup vs baseline: 2.5327x; 1.0538x over previous
#include <cuda_runtime.h>
#include <cuda_bf16.h>
#include <math.h>

// Problem constants
#define Bb   2
#define Tt   2048
#define Dd   2048
#define Hh   16
#define HDd  128
#define DCc  512
#define DRr  64
#define MR   (Bb*Tt)          // 4096 rows

// ---------------- fp32 scratch ------------------------------------------------
__device__ float g_K  [MR*Dd];
__device__ float g_V  [MR*Dd];
__device__ float g_Q  [MR*Dd];
__device__ float g_kr [MR*DRr];
__device__ float g_qr [MR*Hh*DRr];

// ---------------- bf16 hi/lo scratch (activations: row-major [M][K]) ----------
__device__ __nv_bfloat16 g_xh  [MR*Dd],  g_xl  [MR*Dd];
__device__ __nv_bfloat16 g_ckvh[MR*DCc], g_ckvl[MR*DCc];
__device__ __nv_bfloat16 g_cqh [MR*DCc], g_cql [MR*DCc];
__device__ __nv_bfloat16 g_ctxh[MR*Dd],  g_ctxl[MR*Dd];

// ---------------- bf16 hi/lo weights, TRANSPOSED to [N][K] --------------------
__device__ __nv_bfloat16 g_WDKVh[DCc*Dd],       g_WDKVl[DCc*Dd];
__device__ __nv_bfloat16 g_WDQh [DCc*Dd],       g_WDQl [DCc*Dd];
__device__ __nv_bfloat16 g_WUKh [Dd*DCc],       g_WUKl [Dd*DCc];
__device__ __nv_bfloat16 g_WUVh [Dd*DCc],       g_WUVl [Dd*DCc];
__device__ __nv_bfloat16 g_WUQh [Dd*DCc],       g_WUQl [Dd*DCc];
__device__ __nv_bfloat16 g_WKRh [DRr*Dd],       g_WKRl [DRr*Dd];
__device__ __nv_bfloat16 g_WQRh [Hh*DRr*DCc],   g_WQRl [Hh*DRr*DCc];
__device__ __nv_bfloat16 g_WOh  [Dd*Dd],        g_WOl  [Dd*Dd];

// ---------------- attention staging buffers (bf16) -----------------------------
// Qf hi/lo + Kf hi: [b][h][t][192], Vt hi/lo: [b][h][d=128][t]
#define QF_ELEMS (Bb*Hh*Tt*192)
#define VT_ELEMS (Bb*Hh*HDd*Tt)
__device__ __nv_bfloat16 g_QfH[QF_ELEMS], g_QfL[QF_ELEMS];
__device__ __nv_bfloat16 g_KfH[QF_ELEMS];
__device__ __nv_bfloat16 g_VtH[VT_ELEMS], g_VtL[VT_ELEMS];

// ---------------- helpers -------------------------------------------------------
__device__ __forceinline__ void split2(float a, float b, unsigned& hi, unsigned& lo)
{
    unsigned h;
    asm("cvt.rn.bf16x2.f32 %0, %1, %2;" : "=r"(h) : "f"(b), "f"(a));  // lo<=a, hi<=b
    float fa = __uint_as_float(h << 16);
    float fb = __uint_as_float(h & 0xffff0000u);
    unsigned l;
    asm("cvt.rn.bf16x2.f32 %0, %1, %2;" : "=r"(l) : "f"(b - fb), "f"(a - fa));
    hi = h; lo = l;
}

// exp(x) for x <= 0 without MUFU: exp2 split + degree-5 polynomial (~2.4e-6 rel)
__device__ __forceinline__ float fast_exp(float x)
{
    float y = fmaxf(x * 1.4426950408889634f, -80.0f);
    float n = rintf(y);
    float f = y - n;
    float p =           1.3333558146428443e-3f;
    p = fmaf(p, f,      9.6180209931872320e-3f);
    p = fmaf(p, f,      5.5504108664821580e-2f);
    p = fmaf(p, f,      2.4022650695910072e-1f);
    p = fmaf(p, f,      6.9314718055994531e-1f);
    p = fmaf(p, f,      1.0f);
    int e = (int)n;
    return p * __int_as_float((e + 127) << 23);
}

// ---------------- split: fp32 -> (hi, lo) bf16, same layout -------------------
__global__ void split_kernel(const float* __restrict__ in,
                             __nv_bfloat16* __restrict__ hi,
                             __nv_bfloat16* __restrict__ lo, int n4)
{
    int i = blockIdx.x * 256 + threadIdx.x;
    if (i >= n4) return;
    float4 v = ((const float4*)in)[i];
    unsigned h0, l0, h1, l1;
    split2(v.x, v.y, h0, l0);
    split2(v.z, v.w, h1, l1);
    ((unsigned*)hi)[2*i]   = h0;
    ((unsigned*)hi)[2*i+1] = h1;
    ((unsigned*)lo)[2*i]   = l0;
    ((unsigned*)lo)[2*i+1] = l1;
}

// ---------------- split + transpose: fp32 [R][C] -> (hi, lo) bf16 [C][R] ------
__global__ void splitT_kernel(const float* __restrict__ in,
                              __nv_bfloat16* __restrict__ hT,
                              __nv_bfloat16* __restrict__ lT, int R, int C)
{
    __shared__ float t[32][33];
    int bx = blockIdx.x, by = blockIdx.y;
    int tx = threadIdx.x, ty = threadIdx.y;   // 32 x 8
#pragma unroll
    for (int i = 0; i < 32; i += 8)
        t[ty + i][tx] = in[(size_t)(by*32 + ty + i)*C + bx*32 + tx];
    __syncthreads();
#pragma unroll
    for (int i = 0; i < 32; i += 8) {
        float v = t[tx][ty + i];
        int r = bx*32 + ty + i;
        int c = by*32 + tx;
        __nv_bfloat16 h = __float2bfloat16(v);
        hT[(size_t)r*R + c] = h;
        lT[(size_t)r*R + c] = __float2bfloat16(v - __bfloat162float(h));
    }
}

// ---------------- bf16x3 tensor-core GEMM -------------------------------------
#define TBM 128
#define TBN 128
#define TBK 32
#define TKP 40
#define SBUF 20480
#define GEMM_SMEM_BYTES (2*SBUF*2)

__device__ __forceinline__ void mma16816(float* d, const unsigned* a, const unsigned* b)
{
    asm volatile(
        "mma.sync.aligned.m16n8k16.row.col.f32.bf16.bf16.f32 "
        "{%0,%1,%2,%3}, {%4,%5,%6,%7}, {%8,%9}, {%0,%1,%2,%3};"
        : "+f"(d[0]), "+f"(d[1]), "+f"(d[2]), "+f"(d[3])
        : "r"(a[0]), "r"(a[1]), "r"(a[2]), "r"(a[3]),
          "r"(b[0]), "r"(b[1]));
}

__global__ __launch_bounds__(256)
void mma_gemm(const __nv_bfloat16* __restrict__ Ah, const __nv_bfloat16* __restrict__ Al,
              const __nv_bfloat16* __restrict__ Bh, const __nv_bfloat16* __restrict__ Bl,
              float* __restrict__ C,
              __nv_bfloat16* __restrict__ Ch, __nv_bfloat16* __restrict__ Cl,
              int M, int N, int K, const float* __restrict__ bias)
{
    extern __shared__ __nv_bfloat16 sb[];
    const int tid  = threadIdx.x;
    const int lane = tid & 31;
    const int warp = tid >> 5;
    const int wm = warp & 3;
    const int wn = warp >> 2;
    const int row0 = blockIdx.y * TBM;
    const int col0 = blockIdx.x * TBN;

    const int ldr = tid >> 3;
    const int ldc = (tid & 7) * 4;

    float acc[2][8][4];
#pragma unroll
    for (int i = 0; i < 2; i++)
#pragma unroll
        for (int j = 0; j < 8; j++)
#pragma unroll
            for (int r = 0; r < 4; r++) acc[i][j][r] = 0.0f;

    uint2 pah[4], pal[4], pbh[4], pbl[4];

    auto load_tile = [&](int k0) {
#pragma unroll
        for (int p = 0; p < 4; p++) {
            int row = p*32 + ldr;
            size_t aoff = (size_t)(row0 + row) * K + k0 + ldc;
            pah[p] = *(const uint2*)(Ah + aoff);
            pal[p] = *(const uint2*)(Al + aoff);
            if (col0 + row < N) {
                size_t boff = (size_t)(col0 + row) * K + k0 + ldc;
                pbh[p] = *(const uint2*)(Bh + boff);
                pbl[p] = *(const uint2*)(Bl + boff);
            } else {
                pbh[p] = make_uint2(0u, 0u);
                pbl[p] = make_uint2(0u, 0u);
            }
        }
    };
    auto store_tile = [&](int buf) {
        __nv_bfloat16* base = sb + buf * SBUF;
#pragma unroll
        for (int p = 0; p < 4; p++) {
            int row = p*32 + ldr;
            int off = row * TKP + ldc;
            *(uint2*)(base + off)         = pah[p];
            *(uint2*)(base + 5120 + off)  = pal[p];
            *(uint2*)(base + 10240 + off) = pbh[p];
            *(uint2*)(base + 15360 + off) = pbl[p];
        }
    };

    load_tile(0);
    store_tile(0);
    __syncthreads();

    int buf = 0;
    const int a_r = lane >> 2;
    const int a_k = (lane & 3) << 1;

    for (int k0 = 0; k0 < K; k0 += TBK) {
        const bool has_next = (k0 + TBK) < K;
        if (has_next) load_tile(k0 + TBK);

        const __nv_bfloat16* base = sb + buf * SBUF;
#pragma unroll
        for (int kk = 0; kk < TBK; kk += 16) {
            unsigned ah[2][4], al[2][4], bh[8][2], bl[8][2];
#pragma unroll
            for (int i = 0; i < 2; i++) {
#pragma unroll
                for (int r = 0; r < 4; r++) {
                    int rr = wm*32 + i*16 + a_r + ((r & 1) << 3);
                    int cc = kk + a_k + ((r >> 1) << 3);
                    ah[i][r] = *(const unsigned*)(base + rr*TKP + cc);
                    al[i][r] = *(const unsigned*)(base + 5120 + rr*TKP + cc);
                }
            }
#pragma unroll
            for (int j = 0; j < 8; j++) {
#pragma unroll
                for (int r = 0; r < 2; r++) {
                    int nn = wn*64 + j*8 + a_r;
                    int cc = kk + a_k + (r << 3);
                    bh[j][r] = *(const unsigned*)(base + 10240 + nn*TKP + cc);
                    bl[j][r] = *(const unsigned*)(base + 15360 + nn*TKP + cc);
                }
            }
#pragma unroll
            for (int i = 0; i < 2; i++)
#pragma unroll
                for (int j = 0; j < 8; j++) {
                    mma16816(acc[i][j], ah[i], bh[j]);
                    mma16816(acc[i][j], ah[i], bl[j]);
                    mma16816(acc[i][j], al[i], bh[j]);
                }
        }

        if (has_next) store_tile(buf ^ 1);
        __syncthreads();
        buf ^= 1;
    }

#pragma unroll
    for (int i = 0; i < 2; i++) {
        int r_ = row0 + wm*32 + i*16 + (lane >> 2);
#pragma unroll
        for (int j = 0; j < 8; j++) {
            int c_ = col0 + wn*64 + j*8 + ((lane & 3) << 1);
            if (c_ < N) {
                float b0 = bias ? bias[c_]     : 0.0f;
                float b1 = bias ? bias[c_ + 1] : 0.0f;
                float f0 = acc[i][j][0] + b0, f1 = acc[i][j][1] + b1;
                float f2 = acc[i][j][2] + b0, f3 = acc[i][j][3] + b1;
                if (C) {
                    *(float2*)&C[(size_t)r_ * N + c_]       = make_float2(f0, f1);
                    *(float2*)&C[(size_t)(r_ + 8) * N + c_] = make_float2(f2, f3);
                }
                if (Ch) {
                    unsigned h0, l0, h1, l1;
                    split2(f0, f1, h0, l0);
                    split2(f2, f3, h1, l1);
                    *(unsigned*)&Ch[(size_t)r_ * N + c_]       = h0;
                    *(unsigned*)&Cl[(size_t)r_ * N + c_]       = l0;
                    *(unsigned*)&Ch[(size_t)(r_ + 8) * N + c_] = h1;
                    *(unsigned*)&Cl[(size_t)(r_ + 8) * N + c_] = l1;
                }
            }
        }
    }
}

// ---------------- RoPE ----------------------------------------------------------
__device__ __forceinline__ void rope_row(float* p, int t)
{
    float x1[32], x2[32];
#pragma unroll
    for (int i = 0; i < 32; i++) { x1[i] = p[i]; x2[i] = p[i + 32]; }
#pragma unroll 8
    for (int i = 0; i < 32; i++) {
        float inv = powf(10000.0f, -((float)i) / 32.0f);
        float f   = (float)t * inv;
        float s, c;
        sincosf(f, &s, &c);
        p[2 * i]     = x1[i] * c - x2[i] * s;
        p[2 * i + 1] = x1[i] * s + x2[i] * c;
    }
}

__global__ void rope_kr_kernel(float* __restrict__ kr)
{
    int row = blockIdx.x * blockDim.x + threadIdx.x;
    if (row >= MR) return;
    rope_row(kr + (size_t)row * DRr, row % Tt);
}

__global__ void rope_qr_kernel(float* __restrict__ qr)
{
    int idx = blockIdx.x * blockDim.x + threadIdx.x;
    if (idx >= MR * Hh) return;
    int bt = idx / Hh;
    int h  = idx % Hh;
    rope_row(qr + (size_t)bt * (Hh * DRr) + h * DRr, bt % Tt);
}

// ---------------- attention prep: Qf (hi/lo) + Kf (hi) [b][h][t][192] ----------
__device__ __forceinline__ void split_store4(float4 v, __nv_bfloat16* H,
                                             __nv_bfloat16* L, size_t o)
{
    unsigned h0, l0, h1, l1;
    split2(v.x, v.y, h0, l0);
    split2(v.z, v.w, h1, l1);
    ((unsigned*)(H + o))[0] = h0;
    ((unsigned*)(H + o))[1] = h1;
    ((unsigned*)(L + o))[0] = l0;
    ((unsigned*)(L + o))[1] = l1;
}

__global__ void prep_qk_kernel(const float* __restrict__ Q, const float* __restrict__ qr,
                               const float* __restrict__ K, const float* __restrict__ kr,
                               __nv_bfloat16* __restrict__ QfH, __nv_bfloat16* __restrict__ QfL,
                               __nv_bfloat16* __restrict__ KfH)
{
    int idx = blockIdx.x * 256 + threadIdx.x;          // over B*H*T*48
    if (idx >= Bb*Hh*Tt*48) return;
    int d4 = idx % 48;
    int t_ = (idx / 48) % Tt;
    int h  = (idx / (48*Tt)) % Hh;
    int b  =  idx / (48*Tt*Hh);
    int d  = d4 * 4;
    int bt = b*Tt + t_;
    const float scale = rsqrtf(192.0f);

    float4 qv, kv;
    if (d < HDd) {
        qv = *(const float4*)&Q[(size_t)bt*Dd + h*HDd + d];
        kv = *(const float4*)&K[(size_t)bt*Dd + h*HDd + d];
    } else {
        qv = *(const float4*)&qr[(size_t)bt*(Hh*DRr) + h*DRr + (d - HDd)];
        kv = *(const float4*)&kr[(size_t)bt*DRr + (d - HDd)];
    }
    qv.x *= scale; qv.y *= scale; qv.z *= scale; qv.w *= scale;

    size_t o = ((size_t)(b*Hh + h)*Tt + t_)*192 + d;
    split_store4(qv, QfH, QfL, o);
    unsigned kh0, kh1;
    asm("cvt.rn.bf16x2.f32 %0, %1, %2;" : "=r"(kh0) : "f"(kv.y), "f"(kv.x));
    asm("cvt.rn.bf16x2.f32 %0, %1, %2;" : "=r"(kh1) : "f"(kv.w), "f"(kv.z));
    ((unsigned*)(KfH + o))[0] = kh0;
    ((unsigned*)(KfH + o))[1] = kh1;
}

// ---------------- attention prep: V transposed to [b][h][d][t] hi/lo -----------
__global__ void prep_vt_kernel(const float* __restrict__ V,
                               __nv_bfloat16* __restrict__ VtH,
                               __nv_bfloat16* __restrict__ VtL)
{
    __shared__ float t[32][33];
    int t0 = blockIdx.x * 32;
    int d0 = blockIdx.y * 32;
    int bh = blockIdx.z;
    int b = bh / Hh, h = bh % Hh;
    int tx = threadIdx.x, ty = threadIdx.y;   // 32 x 8
#pragma unroll
    for (int i = 0; i < 32; i += 8)
        t[ty + i][tx] = V[(size_t)(b*Tt + t0 + ty + i)*Dd + h*HDd + d0 + tx];
    __syncthreads();
#pragma unroll
    for (int i = 0; i < 32; i += 8) {
        float v = t[tx][ty + i];
        size_t o = ((size_t)bh*HDd + d0 + ty + i)*Tt + t0 + tx;
        __nv_bfloat16 hh = __float2bfloat16(v);
        VtH[o] = hh;
        VtL[o] = __float2bfloat16(v - __bfloat162float(hh));
    }
}

// ---------------- bf16 tensor-core flash attention ------------------------------
// Block: 128 q-rows, 8 warps (16 rows each, warp-local softmax), key tiles of 64.
// S = Qh*Kh + Ql*Kh (Q error-compensated, K single-rounded).
// PV = Ph*Vh + Ph*Vl + Pl*Vh (full x3).
#define FBM 128
#define FBN 64
#define QK_STR 200
#define V_STR  72
#define O_QH 0
#define O_QL (O_QH + FBM*QK_STR)          // 25600
#define O_KH (O_QL + FBM*QK_STR)          // 51200
#define O_VH (O_KH + FBN*QK_STR)          // 64000
#define O_VL (O_VH + HDd*V_STR)           // 73216
#define FATT_SMEM_BF16 (O_VL + HDd*V_STR) // 82432
#define FATT_SMEM_BYTES (FATT_SMEM_BF16*2)// 164864

__global__ __launch_bounds__(256)
void mla_attn_mma(const __nv_bfloat16* __restrict__ QfH, const __nv_bfloat16* __restrict__ QfL,
                  const __nv_bfloat16* __restrict__ KfH,
                  const __nv_bfloat16* __restrict__ VtH, const __nv_bfloat16* __restrict__ VtL,
                  __nv_bfloat16* __restrict__ ctxH, __nv_bfloat16* __restrict__ ctxL)
{
    extern __shared__ __nv_bfloat16 sm2[];
    const int tid  = threadIdx.x;
    const int lane = tid & 31;
    const int warp = tid >> 5;
    const int q0 = blockIdx.x * FBM;
    const int h  = blockIdx.y;
    const int b  = blockIdx.z;
    const int bh = b*Hh + h;
    const int a_r = lane >> 2;
    const int a_k = (lane & 3) << 1;

    // ---- load Q tile (hi+lo) into smem ----
    for (int i = tid; i < FBM*24; i += 256) {
        int row = i / 24, u = (i % 24) * 8;
        size_t g = ((size_t)bh*Tt + q0 + row)*192 + u;
        *(uint4*)(sm2 + O_QH + row*QK_STR + u) = *(const uint4*)(QfH + g);
        *(uint4*)(sm2 + O_QL + row*QK_STR + u) = *(const uint4*)(QfL + g);
    }

    float m0 = -1e30f, m1 = -1e30f, l0 = 0.0f, l1 = 0.0f;
    float acc[16][4];
#pragma unroll
    for (int j = 0; j < 16; j++)
#pragma unroll
        for (int r = 0; r < 4; r++) acc[j][r] = 0.0f;

    for (int k0 = 0; k0 < Tt; k0 += FBN) {
        __syncthreads();
        // ---- load K tile (hi) and V tile (hi+lo, d-major) ----
        for (int i = tid; i < FBN*24; i += 256) {
            int row = i / 24, u = (i % 24) * 8;
            size_t g = ((size_t)bh*Tt + k0 + row)*192 + u;
            *(uint4*)(sm2 + O_KH + row*QK_STR + u) = *(const uint4*)(KfH + g);
        }
        for (int i = tid; i < HDd*8; i += 256) {
            int row = i / 8, u = (i % 8) * 8;
            size_t g = ((size_t)bh*HDd + row)*Tt + k0 + u;
            *(uint4*)(sm2 + O_VH + row*V_STR + u) = *(const uint4*)(VtH + g);
            *(uint4*)(sm2 + O_VL + row*V_STR + u) = *(const uint4*)(VtL + g);
        }
        __syncthreads();

        // ---- S = Qf @ Kf^T (x2: Qh*Kh + Ql*Kh) ----
        float sacc[8][4];
#pragma unroll
        for (int j = 0; j < 8; j++)
#pragma unroll
            for (int r = 0; r < 4; r++) sacc[j][r] = 0.0f;

        for (int kk = 0; kk < 192; kk += 16) {
            unsigned ah[4], al[4];
#pragma unroll
            for (int r = 0; r < 4; r++) {
                int rr = warp*16 + a_r + ((r & 1) << 3);
                int cc = kk + a_k + ((r >> 1) << 3);
                ah[r] = *(const unsigned*)(sm2 + O_QH + rr*QK_STR + cc);
                al[r] = *(const unsigned*)(sm2 + O_QL + rr*QK_STR + cc);
            }
#pragma unroll
            for (int j = 0; j < 8; j++) {
                unsigned kb[2];
#pragma unroll
                for (int r = 0; r < 2; r++) {
                    int nn = j*8 + a_r;
                    int cc = kk + a_k + (r << 3);
                    kb[r] = *(const unsigned*)(sm2 + O_KH + nn*QK_STR + cc);
                }
                mma16816(sacc[j], ah, kb);
                mma16816(sacc[j], al, kb);
            }
        }

        // ---- warp-local online softmax ----
        float mx0 = -1e30f, mx1 = -1e30f;
#pragma unroll
        for (int j = 0; j < 8; j++) {
            mx0 = fmaxf(mx0, fmaxf(sacc[j][0], sacc[j][1]));
            mx1 = fmaxf(mx1, fmaxf(sacc[j][2], sacc[j][3]));
        }
        mx0 = fmaxf(mx0, __shfl_xor_sync(0xffffffffu, mx0, 1));
        mx0 = fmaxf(mx0, __shfl_xor_sync(0xffffffffu, mx0, 2));
        mx1 = fmaxf(mx1, __shfl_xor_sync(0xffffffffu, mx1, 1));
        mx1 = fmaxf(mx1, __shfl_xor_sync(0xffffffffu, mx1, 2));

        float mn0 = fmaxf(m0, mx0), mn1 = fmaxf(m1, mx1);
        float al0 = fast_exp(m0 - mn0), al1 = fast_exp(m1 - mn1);
        m0 = mn0; m1 = mn1;

        float s0 = 0.0f, s1 = 0.0f;
#pragma unroll
        for (int j = 0; j < 8; j++) {
            sacc[j][0] = fast_exp(sacc[j][0] - mn0); s0 += sacc[j][0];
            sacc[j][1] = fast_exp(sacc[j][1] - mn0); s0 += sacc[j][1];
            sacc[j][2] = fast_exp(sacc[j][2] - mn1); s1 += sacc[j][2];
            sacc[j][3] = fast_exp(sacc[j][3] - mn1); s1 += sacc[j][3];
        }
        s0 += __shfl_xor_sync(0xffffffffu, s0, 1);
        s0 += __shfl_xor_sync(0xffffffffu, s0, 2);
        s1 += __shfl_xor_sync(0xffffffffu, s1, 1);
        s1 += __shfl_xor_sync(0xffffffffu, s1, 2);
        l0 = l0*al0 + s0;
        l1 = l1*al1 + s1;

#pragma unroll
        for (int j = 0; j < 16; j++) {
            acc[j][0] *= al0; acc[j][1] *= al0;
            acc[j][2] *= al1; acc[j][3] *= al1;
        }

        // ---- acc += P @ V  (P split hi/lo; x3) ----
#pragma unroll
        for (int c = 0; c < 4; c++) {
            unsigned pah[4], pal[4];
            split2(sacc[2*c][0],   sacc[2*c][1],   pah[0], pal[0]);
            split2(sacc[2*c][2],   sacc[2*c][3],   pah[1], pal[1]);
            split2(sacc[2*c+1][0], sacc[2*c+1][1], pah[2], pal[2]);
            split2(sacc[2*c+1][2], sacc[2*c+1][3], pah[3], pal[3]);
#pragma unroll
            for (int j2 = 0; j2 < 16; j2++) {
                unsigned vh[2], vl[2];
#pragma unroll
                for (int r = 0; r < 2; r++) {
                    int nn = j2*8 + a_r;
                    int cc = c*16 + a_k + (r << 3);
                    vh[r] = *(const unsigned*)(sm2 + O_VH + nn*V_STR + cc);
                    vl[r] = *(const unsigned*)(sm2 + O_VL + nn*V_STR + cc);
                }
                mma16816(acc[j2], pah, vh);
                mma16816(acc[j2], pah, vl);
                mma16816(acc[j2], pal, vh);
            }
        }
    }

    // ---- epilogue: normalize, write ctx hi/lo bf16 directly ----
    float i0 = 1.0f / l0, i1 = 1.0f / l1;
    int gr = b*Tt + q0 + warp*16 + a_r;
#pragma unroll
    for (int j2 = 0; j2 < 16; j2++) {
        int col = h*HDd + j2*8 + a_k;
        unsigned h0, lo0, h1, lo1;
        split2(acc[j2][0]*i0, acc[j2][1]*i0, h0, lo0);
        split2(acc[j2][2]*i1, acc[j2][3]*i1, h1, lo1);
        *(unsigned*)&ctxH[(size_t)gr*Dd + col]     = h0;
        *(unsigned*)&ctxL[(size_t)gr*Dd + col]     = lo0;
        *(unsigned*)&ctxH[(size_t)(gr+8)*Dd + col] = h1;
        *(unsigned*)&ctxL[(size_t)(gr+8)*Dd + col] = lo1;
    }
}

// ---------------- host driver ---------------------------------------------------
static inline void launch_mma(const __nv_bfloat16* Ah, const __nv_bfloat16* Al,
                              const __nv_bfloat16* Bh, const __nv_bfloat16* Bl,
                              float* C, __nv_bfloat16* Ch, __nv_bfloat16* Cl,
                              int M, int N, int K, const float* bias)
{
    dim3 grid((N + TBN - 1) / TBN, M / TBM);
    mma_gemm<<<grid, 256, GEMM_SMEM_BYTES>>>(Ah, Al, Bh, Bl, C, Ch, Cl, M, N, K, bias);
}

static inline void launch_split(const float* in, __nv_bfloat16* hi, __nv_bfloat16* lo, int n)
{
    int n4 = n / 4;
    split_kernel<<<(n4 + 255) / 256, 256>>>(in, hi, lo, n4);
}

static inline void launch_splitT(const float* in, __nv_bfloat16* hT, __nv_bfloat16* lT,
                                 int R, int C)
{
    dim3 grid(C / 32, R / 32);
    splitT_kernel<<<grid, dim3(32, 8)>>>(in, hT, lT, R, C);
}

extern "C" void kernel_launch(void* const* d_in, const int* in_sizes, int n_in,
                              void* d_out, int out_size)
{
    const float* x     = (const float*)d_in[0];
    const float* W_DKV = (const float*)d_in[1];
    const float* W_DQ  = (const float*)d_in[2];
    const float* W_UK  = (const float*)d_in[3];
    const float* W_UV  = (const float*)d_in[4];
    const float* W_UQ  = (const float*)d_in[5];
    const float* W_KR  = (const float*)d_in[6];
    const float* W_QR  = (const float*)d_in[7];
    const float* W_O   = (const float*)d_in[8];
    const float* b_O   = (const float*)d_in[9];
    float* out = (float*)d_out;

    float *Kp, *Vp, *Qp, *krp, *qrp;
    cudaGetSymbolAddress((void**)&Kp,   g_K);
    cudaGetSymbolAddress((void**)&Vp,   g_V);
    cudaGetSymbolAddress((void**)&Qp,   g_Q);
    cudaGetSymbolAddress((void**)&krp,  g_kr);
    cudaGetSymbolAddress((void**)&qrp,  g_qr);

    __nv_bfloat16 *xh, *xl, *ckvh, *ckvl, *cqh, *cql, *ctxh, *ctxl;
    cudaGetSymbolAddress((void**)&xh,   g_xh);   cudaGetSymbolAddress((void**)&xl,   g_xl);
    cudaGetSymbolAddress((void**)&ckvh, g_ckvh); cudaGetSymbolAddress((void**)&ckvl, g_ckvl);
    cudaGetSymbolAddress((void**)&cqh,  g_cqh);  cudaGetSymbolAddress((void**)&cql,  g_cql);
    cudaGetSymbolAddress((void**)&ctxh, g_ctxh); cudaGetSymbolAddress((void**)&ctxl, g_ctxl);

    __nv_bfloat16 *wdkvh, *wdkvl, *wdqh, *wdql, *wukh, *wukl, *wuvh, *wuvl,
                  *wuqh, *wuql, *wkrh, *wkrl, *wqrh, *wqrl, *woh, *wol;
    cudaGetSymbolAddress((void**)&wdkvh, g_WDKVh); cudaGetSymbolAddress((void**)&wdkvl, g_WDKVl);
    cudaGetSymbolAddress((void**)&wdqh,  g_WDQh);  cudaGetSymbolAddress((void**)&wdql,  g_WDQl);
    cudaGetSymbolAddress((void**)&wukh,  g_WUKh);  cudaGetSymbolAddress((void**)&wukl,  g_WUKl);
    cudaGetSymbolAddress((void**)&wuvh,  g_WUVh);  cudaGetSymbolAddress((void**)&wuvl,  g_WUVl);
    cudaGetSymbolAddress((void**)&wuqh,  g_WUQh);  cudaGetSymbolAddress((void**)&wuql,  g_WUQl);
    cudaGetSymbolAddress((void**)&wkrh,  g_WKRh);  cudaGetSymbolAddress((void**)&wkrl,  g_WKRl);
    cudaGetSymbolAddress((void**)&wqrh,  g_WQRh);  cudaGetSymbolAddress((void**)&wqrl,  g_WQRl);
    cudaGetSymbolAddress((void**)&woh,   g_WOh);   cudaGetSymbolAddress((void**)&wol,   g_WOl);

    __nv_bfloat16 *qfh, *qfl, *kfh, *vth, *vtl;
    cudaGetSymbolAddress((void**)&qfh, g_QfH); cudaGetSymbolAddress((void**)&qfl, g_QfL);
    cudaGetSymbolAddress((void**)&kfh, g_KfH);
    cudaGetSymbolAddress((void**)&vth, g_VtH); cudaGetSymbolAddress((void**)&vtl, g_VtL);

    cudaFuncSetAttribute(mma_gemm, cudaFuncAttributeMaxDynamicSharedMemorySize,
                         GEMM_SMEM_BYTES);
    cudaFuncSetAttribute(mla_attn_mma, cudaFuncAttributeMaxDynamicSharedMemorySize,
                         FATT_SMEM_BYTES);

    // ---- split inputs / weights (weights transposed to [N][K]) ----
    launch_split(x, xh, xl, MR * Dd);
    launch_splitT(W_DKV, wdkvh, wdkvl, Dd, DCc);
    launch_splitT(W_DQ,  wdqh,  wdql,  Dd, DCc);
    launch_splitT(W_UK,  wukh,  wukl,  DCc, Dd);
    launch_splitT(W_UV,  wuvh,  wuvl,  DCc, Dd);
    launch_splitT(W_UQ,  wuqh,  wuql,  DCc, Dd);
    launch_splitT(W_KR,  wkrh,  wkrl,  Dd, DRr);
    launch_splitT(W_QR,  wqrh,  wqrl,  DCc, Hh * DRr);
    launch_splitT(W_O,   woh,   wol,   Dd, Dd);

    // ---- down-projections (latents written directly as hi/lo) + rope key ----
    launch_mma(xh, xl, wdkvh, wdkvl, nullptr, ckvh, ckvl, MR, DCc, Dd, nullptr);
    launch_mma(xh, xl, wdqh,  wdql,  nullptr, cqh,  cql,  MR, DCc, Dd, nullptr);
    launch_mma(xh, xl, wkrh,  wkrl,  krp, nullptr, nullptr, MR, DRr, Dd, nullptr);
    rope_kr_kernel<<<(MR + 127) / 128, 128>>>(krp);

    // ---- up-projections ----
    launch_mma(ckvh, ckvl, wukh, wukl, Kp,  nullptr, nullptr, MR, Dd,       DCc, nullptr);
    launch_mma(ckvh, ckvl, wuvh, wuvl, Vp,  nullptr, nullptr, MR, Dd,       DCc, nullptr);
    launch_mma(cqh,  cql,  wuqh, wuql, Qp,  nullptr, nullptr, MR, Dd,       DCc, nullptr);
    launch_mma(cqh,  cql,  wqrh, wqrl, qrp, nullptr, nullptr, MR, Hh * DRr, DCc, nullptr);
    rope_qr_kernel<<<(MR * Hh + 127) / 128, 128>>>(qrp);

    // ---- stage attention operands ----
    prep_qk_kernel<<<(Bb*Hh*Tt*48 + 255) / 256, 256>>>(Qp, qrp, Kp, krp,
                                                       qfh, qfl, kfh);
    prep_vt_kernel<<<dim3(Tt/32, HDd/32, Bb*Hh), dim3(32, 8)>>>(Vp, vth, vtl);

    // ---- tensor-core flash attention (ctx written as hi/lo) ----
    mla_attn_mma<<<dim3(Tt/FBM, Hh, Bb), 256, FATT_SMEM_BYTES>>>(
        qfh, qfl, kfh, vth, vtl, ctxh, ctxl);

    // ---- output projection + bias ----
    launch_mma(ctxh, ctxl, woh, wol, out, nullptr, nullptr, MR, Dd, Dd, b_O);
}